// round 1
// baseline (speedup 1.0000x reference)
#include <cuda_runtime.h>

// ---------------------------------------------------------------------------
// Fused MHA block: QKV GEMM -> flash attention -> output projection.
// Shapes: B=2, N=2048, EMBED=1024, HEADS=16, HDIM=64. All fp32.
// ---------------------------------------------------------------------------

#define BATCH  2
#define SEQ    2048
#define EMBED  1024
#define HEADS  16
#define HDIM   64
#define MTOK   (BATCH * SEQ)      // 4096
#define QKVN   (3 * EMBED)        // 3072
#define SCALE  0.125f             // HDIM^-0.5

// Scratch (allocation-free rule: __device__ globals).
__device__ float g_Q[BATCH * HEADS * SEQ * HDIM];   // [B,H,N,Dh]
__device__ float g_K[BATCH * HEADS * SEQ * HDIM];
__device__ float g_V[BATCH * HEADS * SEQ * HDIM];
__device__ float g_O[BATCH * SEQ * EMBED];          // attention output [B,N,EMBED]

// ---------------------------------------------------------------------------
// GEMM: C[M,N] = A[M,K] @ W[N,K]^T + bias[N]
// 128x128 block, BK=16, 256 threads, 8x8 per-thread tile.
// MODE 0: scatter into g_Q/g_K/g_V ([B,H,N,Dh]).  MODE 1: write to out.
// ---------------------------------------------------------------------------
template <int MODE>
__global__ __launch_bounds__(256)
void gemm_xwT(const float* __restrict__ A, const float* __restrict__ W,
              const float* __restrict__ bias, float* __restrict__ out,
              int M, int N, int K)
{
    constexpr int BM = 128, BN = 128, BK = 16;
    __shared__ float As[BK][BM];
    __shared__ float Bs[BK][BN];

    const int tid = threadIdx.x;
    const int m0 = blockIdx.y * BM;
    const int n0 = blockIdx.x * BN;

    const int lrow = tid >> 2;          // 0..63
    const int lcol = (tid & 3) << 2;    // 0,4,8,12

    const int tx = tid & 15;            // output col group
    const int ty = tid >> 4;            // output row group

    float acc[8][8];
#pragma unroll
    for (int i = 0; i < 8; ++i)
#pragma unroll
        for (int j = 0; j < 8; ++j) acc[i][j] = 0.f;

    for (int k0 = 0; k0 < K; k0 += BK) {
#pragma unroll
        for (int r = 0; r < 2; ++r) {
            const int row = lrow + r * 64;
            float4 a = *(const float4*)&A[(size_t)(m0 + row) * K + k0 + lcol];
            As[lcol + 0][row] = a.x;
            As[lcol + 1][row] = a.y;
            As[lcol + 2][row] = a.z;
            As[lcol + 3][row] = a.w;
            float4 b = *(const float4*)&W[(size_t)(n0 + row) * K + k0 + lcol];
            Bs[lcol + 0][row] = b.x;
            Bs[lcol + 1][row] = b.y;
            Bs[lcol + 2][row] = b.z;
            Bs[lcol + 3][row] = b.w;
        }
        __syncthreads();

#pragma unroll
        for (int k = 0; k < BK; ++k) {
            float ra[8], rb[8];
            *(float4*)&ra[0] = *(const float4*)&As[k][ty * 8];
            *(float4*)&ra[4] = *(const float4*)&As[k][ty * 8 + 4];
            *(float4*)&rb[0] = *(const float4*)&Bs[k][tx * 8];
            *(float4*)&rb[4] = *(const float4*)&Bs[k][tx * 8 + 4];
#pragma unroll
            for (int i = 0; i < 8; ++i)
#pragma unroll
                for (int j = 0; j < 8; ++j)
                    acc[i][j] = fmaf(ra[i], rb[j], acc[i][j]);
        }
        __syncthreads();
    }

#pragma unroll
    for (int i = 0; i < 8; ++i) {
        const int m = m0 + ty * 8 + i;
#pragma unroll
        for (int j = 0; j < 8; ++j) {
            const int n = n0 + tx * 8 + j;
            float v = acc[i][j] + bias[n];
            if (MODE == 0) {
                // n in [0,3072): which(q/k/v), head, dh.  m = b*SEQ + token.
                const int which = n >> 10;
                const int rem = n & 1023;
                const int h = rem >> 6;
                const int dh = rem & 63;
                const int b = m >> 11;
                const int t = m & 2047;
                float* dst = (which == 0) ? g_Q : (which == 1) ? g_K : g_V;
                dst[(((size_t)(b * HEADS + h) * SEQ) + t) * HDIM + dh] = v;
            } else {
                out[(size_t)m * N + n] = v;
            }
        }
    }
}

// ---------------------------------------------------------------------------
// Flash attention: one block per (b*h, q-tile of 64). 256 threads (16x16),
// each thread owns a 4x4 tile of the 64x64 score block. Online softmax.
// Smem: Qt (transposed, pre-scaled), KtPs (K transposed, reused as P), Vs.
// ---------------------------------------------------------------------------
__global__ __launch_bounds__(256)
void flash_attn()
{
    __shared__ float Qt[64][64];    // [d][row]
    __shared__ float KtPs[64][64];  // K: [d][col]; reused as P: [row][kvcol]
    __shared__ float Vs[64][64];    // [kvcol][d]

    const int bh = blockIdx.y;              // 0..31  (b*HEADS + h)
    const int q0 = blockIdx.x * 64;
    const float* Qp = g_Q + (size_t)bh * SEQ * HDIM;
    const float* Kp = g_K + (size_t)bh * SEQ * HDIM;
    const float* Vp = g_V + (size_t)bh * SEQ * HDIM;

    const int tid = threadIdx.x;
    const int tx = tid & 15;   // cols 4*tx..+3
    const int ty = tid >> 4;   // rows 4*ty..+3

    // Load Q tile transposed, pre-scaled.
#pragma unroll
    for (int it = 0; it < 4; ++it) {
        const int r = (tid >> 4) + it * 16;
        const int c = (tid & 15) * 4;
        float4 q = *(const float4*)&Qp[(size_t)(q0 + r) * HDIM + c];
        Qt[c + 0][r] = q.x * SCALE;
        Qt[c + 1][r] = q.y * SCALE;
        Qt[c + 2][r] = q.z * SCALE;
        Qt[c + 3][r] = q.w * SCALE;
    }

    float m_i[4], l_i[4], o_[4][4];
#pragma unroll
    for (int i = 0; i < 4; ++i) {
        m_i[i] = -1e30f; l_i[i] = 0.f;
#pragma unroll
        for (int j = 0; j < 4; ++j) o_[i][j] = 0.f;
    }

    const unsigned FULL = 0xffffffffu;

    for (int kt = 0; kt < SEQ / 64; ++kt) {
        __syncthreads();   // previous iteration's P/V reads done
        // Load K (transposed) and V (straight).
#pragma unroll
        for (int it = 0; it < 4; ++it) {
            const int r = (tid >> 4) + it * 16;
            const int c = (tid & 15) * 4;
            float4 kk = *(const float4*)&Kp[(size_t)(kt * 64 + r) * HDIM + c];
            KtPs[c + 0][r] = kk.x;
            KtPs[c + 1][r] = kk.y;
            KtPs[c + 2][r] = kk.z;
            KtPs[c + 3][r] = kk.w;
            float4 vv = *(const float4*)&Vp[(size_t)(kt * 64 + r) * HDIM + c];
            *(float4*)&Vs[r][c] = vv;
        }
        __syncthreads();

        // S = (Q*scale) @ K^T   (4x4 per thread)
        float s[4][4];
#pragma unroll
        for (int i = 0; i < 4; ++i)
#pragma unroll
            for (int j = 0; j < 4; ++j) s[i][j] = 0.f;
#pragma unroll 8
        for (int d = 0; d < 64; ++d) {
            float4 qa = *(const float4*)&Qt[d][ty * 4];
            float4 kb = *(const float4*)&KtPs[d][tx * 4];
            float qv[4] = {qa.x, qa.y, qa.z, qa.w};
            float kv[4] = {kb.x, kb.y, kb.z, kb.w};
#pragma unroll
            for (int i = 0; i < 4; ++i)
#pragma unroll
                for (int j = 0; j < 4; ++j)
                    s[i][j] = fmaf(qv[i], kv[j], s[i][j]);
        }

        __syncthreads();   // done reading K; KtPs becomes P

        // Online softmax update per owned row.
#pragma unroll
        for (int i = 0; i < 4; ++i) {
            float mx = fmaxf(fmaxf(s[i][0], s[i][1]), fmaxf(s[i][2], s[i][3]));
#pragma unroll
            for (int off = 1; off < 16; off <<= 1)
                mx = fmaxf(mx, __shfl_xor_sync(FULL, mx, off));
            const float mnew = fmaxf(m_i[i], mx);
            const float alpha = __expf(m_i[i] - mnew);
            float rs = 0.f;
#pragma unroll
            for (int j = 0; j < 4; ++j) {
                s[i][j] = __expf(s[i][j] - mnew);
                rs += s[i][j];
            }
#pragma unroll
            for (int off = 1; off < 16; off <<= 1)
                rs += __shfl_xor_sync(FULL, rs, off);
            l_i[i] = alpha * l_i[i] + rs;
            m_i[i] = mnew;
#pragma unroll
            for (int j = 0; j < 4; ++j) o_[i][j] *= alpha;
        }

        // Stage P to smem (row-major [row][kvcol]).
#pragma unroll
        for (int i = 0; i < 4; ++i)
            *(float4*)&KtPs[ty * 4 + i][tx * 4] =
                make_float4(s[i][0], s[i][1], s[i][2], s[i][3]);
        __syncthreads();

        // O += P @ V
#pragma unroll 4
        for (int kv = 0; kv < 64; ++kv) {
            float4 v4 = *(const float4*)&Vs[kv][tx * 4];
#pragma unroll
            for (int i = 0; i < 4; ++i) {
                const float p = KtPs[ty * 4 + i][kv];
                o_[i][0] = fmaf(p, v4.x, o_[i][0]);
                o_[i][1] = fmaf(p, v4.y, o_[i][1]);
                o_[i][2] = fmaf(p, v4.z, o_[i][2]);
                o_[i][3] = fmaf(p, v4.w, o_[i][3]);
            }
        }
    }

    // Normalize and write to g_O [B,N,EMBED].
    const int h = bh & (HEADS - 1);
    const int b = bh >> 4;
#pragma unroll
    for (int i = 0; i < 4; ++i) {
        const int t = q0 + ty * 4 + i;
        const float inv = 1.0f / l_i[i];
#pragma unroll
        for (int j = 0; j < 4; ++j)
            g_O[((size_t)(b * SEQ + t)) * EMBED + h * HDIM + tx * 4 + j] =
                o_[i][j] * inv;
    }
}

// ---------------------------------------------------------------------------
extern "C" void kernel_launch(void* const* d_in, const int* in_sizes, int n_in,
                              void* d_out, int out_size)
{
    const float* x      = (const float*)d_in[0];
    const float* w_qkv  = (const float*)d_in[1];
    const float* b_qkv  = (const float*)d_in[2];
    const float* w_proj = (const float*)d_in[3];
    const float* b_proj = (const float*)d_in[4];
    float* out = (float*)d_out;

    float* gO = nullptr;
    cudaGetSymbolAddress((void**)&gO, g_O);

    // 1) QKV projection (scatter into g_Q/g_K/g_V)
    {
        dim3 grid(QKVN / 128, MTOK / 128);
        gemm_xwT<0><<<grid, 256>>>(x, w_qkv, b_qkv, nullptr, MTOK, QKVN, EMBED);
    }
    // 2) Flash attention -> g_O
    {
        dim3 grid(SEQ / 64, BATCH * HEADS);
        flash_attn<<<grid, 256>>>();
    }
    // 3) Output projection
    {
        dim3 grid(EMBED / 128, MTOK / 128);
        gemm_xwT<1><<<grid, 256>>>(gO, w_proj, b_proj, out, MTOK, EMBED, EMBED);
    }
}

// round 2
// speedup vs baseline: 1.4728x; 1.4728x over previous
#include <cuda_runtime.h>

// ---------------------------------------------------------------------------
// Fused MHA block: QKV GEMM (tf32 mma) -> flash attention (fp32) -> proj (tf32 mma).
// Shapes: B=2, N=2048, EMBED=1024, HEADS=16, HDIM=64.
// ---------------------------------------------------------------------------

#define BATCH  2
#define SEQ    2048
#define EMBED  1024
#define HEADS  16
#define HDIM   64
#define MTOK   (BATCH * SEQ)      // 4096
#define QKVN   (3 * EMBED)        // 3072
#define SCALE  0.125f             // HDIM^-0.5

// Scratch (allocation-free rule: __device__ globals).
__device__ float g_Q[BATCH * HEADS * SEQ * HDIM];   // [B,H,N,Dh]
__device__ float g_K[BATCH * HEADS * SEQ * HDIM];
__device__ float g_V[BATCH * HEADS * SEQ * HDIM];
__device__ float g_O[BATCH * SEQ * EMBED];          // attention output [B,N,EMBED]

// ---------------------------------------------------------------------------
// tf32 helpers
// ---------------------------------------------------------------------------
__device__ __forceinline__ unsigned f2tf(float f) {
    unsigned r;
    asm("cvt.rna.tf32.f32 %0, %1;" : "=r"(r) : "f"(f));
    return r;
}

__device__ __forceinline__ void mma_tf32(float* c, const unsigned* a, const unsigned* b) {
    asm volatile(
        "mma.sync.aligned.m16n8k8.row.col.f32.tf32.tf32.f32 "
        "{%0,%1,%2,%3}, {%4,%5,%6,%7}, {%8,%9}, {%0,%1,%2,%3};\n"
        : "+f"(c[0]), "+f"(c[1]), "+f"(c[2]), "+f"(c[3])
        : "r"(a[0]), "r"(a[1]), "r"(a[2]), "r"(a[3]),
          "r"(b[0]), "r"(b[1]));
}

// ---------------------------------------------------------------------------
// GEMM: C[M,N] = A[M,K] @ W[N,K]^T + bias[N]   (tf32 tensor cores)
// 128x128 CTA tile, BK=32, 256 threads = 8 warps (4 in M x 2 in N).
// Warp tile 32x64: 2 m-frags x 8 n-frags of m16n8k8.
// MODE 0: scatter into g_Q/g_K/g_V ([B,H,N,Dh]).  MODE 1: write to out.
// ---------------------------------------------------------------------------
template <int MODE>
__global__ __launch_bounds__(256)
void gemm_mma(const float* __restrict__ A, const float* __restrict__ W,
              const float* __restrict__ bias, float* __restrict__ out,
              int M, int N, int K)
{
    constexpr int BM = 128, BN = 128, BK = 32;
    constexpr int LDT = BK + 4;   // 36 words: conflict-free fragment loads
    __shared__ unsigned As[BM * LDT];
    __shared__ unsigned Bs[BN * LDT];

    const int tid  = threadIdx.x;
    const int wid  = tid >> 5;
    const int lane = tid & 31;
    const int g    = lane >> 2;   // groupID 0..7
    const int t    = lane & 3;    // threadID-in-group 0..3

    const int wm0 = (wid & 3) * 32;   // warp M offset in tile
    const int wn0 = (wid >> 2) * 64;  // warp N offset in tile

    const int m0 = blockIdx.y * BM;
    const int n0 = blockIdx.x * BN;

    float acc[2][8][4];
#pragma unroll
    for (int mi = 0; mi < 2; ++mi)
#pragma unroll
        for (int nj = 0; nj < 8; ++nj)
#pragma unroll
            for (int r = 0; r < 4; ++r) acc[mi][nj][r] = 0.f;

    const int srow = tid >> 3;        // 0..31
    const int scol = (tid & 7) * 4;   // 0..28

    for (int k0 = 0; k0 < K; k0 += BK) {
        // Stage tiles (row-major, padded), converting to tf32.
#pragma unroll
        for (int r = 0; r < 4; ++r) {
            const int row = srow + 32 * r;
            float4 a = *(const float4*)&A[(size_t)(m0 + row) * K + k0 + scol];
            uint4 at = make_uint4(f2tf(a.x), f2tf(a.y), f2tf(a.z), f2tf(a.w));
            *(uint4*)&As[row * LDT + scol] = at;
            float4 b = *(const float4*)&W[(size_t)(n0 + row) * K + k0 + scol];
            uint4 bt = make_uint4(f2tf(b.x), f2tf(b.y), f2tf(b.z), f2tf(b.w));
            *(uint4*)&Bs[row * LDT + scol] = bt;
        }
        __syncthreads();

#pragma unroll
        for (int ks = 0; ks < BK / 8; ++ks) {
            const int kk = ks * 8;
            unsigned a[2][4], b[8][2];
#pragma unroll
            for (int mi = 0; mi < 2; ++mi) {
                const int mb = wm0 + mi * 16;
                a[mi][0] = As[(mb + g)     * LDT + kk + t];
                a[mi][1] = As[(mb + g + 8) * LDT + kk + t];
                a[mi][2] = As[(mb + g)     * LDT + kk + t + 4];
                a[mi][3] = As[(mb + g + 8) * LDT + kk + t + 4];
            }
#pragma unroll
            for (int nj = 0; nj < 8; ++nj) {
                const int nb = wn0 + nj * 8 + g;
                b[nj][0] = Bs[nb * LDT + kk + t];
                b[nj][1] = Bs[nb * LDT + kk + t + 4];
            }
#pragma unroll
            for (int mi = 0; mi < 2; ++mi)
#pragma unroll
                for (int nj = 0; nj < 8; ++nj)
                    mma_tf32(acc[mi][nj], a[mi], b[nj]);
        }
        __syncthreads();
    }

    // Epilogue. C frag mapping: c0:(g,2t) c1:(g,2t+1) c2:(g+8,2t) c3:(g+8,2t+1)
#pragma unroll
    for (int mi = 0; mi < 2; ++mi) {
#pragma unroll
        for (int nj = 0; nj < 8; ++nj) {
#pragma unroll
            for (int r = 0; r < 4; ++r) {
                const int m = m0 + wm0 + mi * 16 + g + (r >= 2 ? 8 : 0);
                const int n = n0 + wn0 + nj * 8 + 2 * t + (r & 1);
                float v = acc[mi][nj][r] + bias[n];
                if (MODE == 0) {
                    const int which = n >> 10;        // q/k/v
                    const int rem   = n & 1023;
                    const int h     = rem >> 6;
                    const int dh    = rem & 63;
                    const int b_    = m >> 11;
                    const int tkn   = m & 2047;
                    float* dst = (which == 0) ? g_Q : (which == 1) ? g_K : g_V;
                    dst[(((size_t)(b_ * HEADS + h) * SEQ) + tkn) * HDIM + dh] = v;
                } else {
                    out[(size_t)m * N + n] = v;
                }
            }
        }
    }
}

// ---------------------------------------------------------------------------
// Flash attention (fp32, unchanged from round 1): one block per (b*h, 64 q rows).
// ---------------------------------------------------------------------------
__global__ __launch_bounds__(256)
void flash_attn()
{
    __shared__ float Qt[64][64];    // [d][row]
    __shared__ float KtPs[64][64];  // K: [d][col]; reused as P: [row][kvcol]
    __shared__ float Vs[64][64];    // [kvcol][d]

    const int bh = blockIdx.y;
    const int q0 = blockIdx.x * 64;
    const float* Qp = g_Q + (size_t)bh * SEQ * HDIM;
    const float* Kp = g_K + (size_t)bh * SEQ * HDIM;
    const float* Vp = g_V + (size_t)bh * SEQ * HDIM;

    const int tid = threadIdx.x;
    const int tx = tid & 15;
    const int ty = tid >> 4;

#pragma unroll
    for (int it = 0; it < 4; ++it) {
        const int r = (tid >> 4) + it * 16;
        const int c = (tid & 15) * 4;
        float4 q = *(const float4*)&Qp[(size_t)(q0 + r) * HDIM + c];
        Qt[c + 0][r] = q.x * SCALE;
        Qt[c + 1][r] = q.y * SCALE;
        Qt[c + 2][r] = q.z * SCALE;
        Qt[c + 3][r] = q.w * SCALE;
    }

    float m_i[4], l_i[4], o_[4][4];
#pragma unroll
    for (int i = 0; i < 4; ++i) {
        m_i[i] = -1e30f; l_i[i] = 0.f;
#pragma unroll
        for (int j = 0; j < 4; ++j) o_[i][j] = 0.f;
    }

    const unsigned FULL = 0xffffffffu;

    for (int kt = 0; kt < SEQ / 64; ++kt) {
        __syncthreads();
#pragma unroll
        for (int it = 0; it < 4; ++it) {
            const int r = (tid >> 4) + it * 16;
            const int c = (tid & 15) * 4;
            float4 kk = *(const float4*)&Kp[(size_t)(kt * 64 + r) * HDIM + c];
            KtPs[c + 0][r] = kk.x;
            KtPs[c + 1][r] = kk.y;
            KtPs[c + 2][r] = kk.z;
            KtPs[c + 3][r] = kk.w;
            float4 vv = *(const float4*)&Vp[(size_t)(kt * 64 + r) * HDIM + c];
            *(float4*)&Vs[r][c] = vv;
        }
        __syncthreads();

        float s[4][4];
#pragma unroll
        for (int i = 0; i < 4; ++i)
#pragma unroll
            for (int j = 0; j < 4; ++j) s[i][j] = 0.f;
#pragma unroll 8
        for (int d = 0; d < 64; ++d) {
            float4 qa = *(const float4*)&Qt[d][ty * 4];
            float4 kb = *(const float4*)&KtPs[d][tx * 4];
            float qv[4] = {qa.x, qa.y, qa.z, qa.w};
            float kv[4] = {kb.x, kb.y, kb.z, kb.w};
#pragma unroll
            for (int i = 0; i < 4; ++i)
#pragma unroll
                for (int j = 0; j < 4; ++j)
                    s[i][j] = fmaf(qv[i], kv[j], s[i][j]);
        }

        __syncthreads();

#pragma unroll
        for (int i = 0; i < 4; ++i) {
            float mx = fmaxf(fmaxf(s[i][0], s[i][1]), fmaxf(s[i][2], s[i][3]));
#pragma unroll
            for (int off = 1; off < 16; off <<= 1)
                mx = fmaxf(mx, __shfl_xor_sync(FULL, mx, off));
            const float mnew = fmaxf(m_i[i], mx);
            const float alpha = __expf(m_i[i] - mnew);
            float rs = 0.f;
#pragma unroll
            for (int j = 0; j < 4; ++j) {
                s[i][j] = __expf(s[i][j] - mnew);
                rs += s[i][j];
            }
#pragma unroll
            for (int off = 1; off < 16; off <<= 1)
                rs += __shfl_xor_sync(FULL, rs, off);
            l_i[i] = alpha * l_i[i] + rs;
            m_i[i] = mnew;
#pragma unroll
            for (int j = 0; j < 4; ++j) o_[i][j] *= alpha;
        }

#pragma unroll
        for (int i = 0; i < 4; ++i)
            *(float4*)&KtPs[ty * 4 + i][tx * 4] =
                make_float4(s[i][0], s[i][1], s[i][2], s[i][3]);
        __syncthreads();

#pragma unroll 4
        for (int kv = 0; kv < 64; ++kv) {
            float4 v4 = *(const float4*)&Vs[kv][tx * 4];
#pragma unroll
            for (int i = 0; i < 4; ++i) {
                const float p = KtPs[ty * 4 + i][kv];
                o_[i][0] = fmaf(p, v4.x, o_[i][0]);
                o_[i][1] = fmaf(p, v4.y, o_[i][1]);
                o_[i][2] = fmaf(p, v4.z, o_[i][2]);
                o_[i][3] = fmaf(p, v4.w, o_[i][3]);
            }
        }
    }

    const int h = bh & (HEADS - 1);
    const int b = bh >> 4;
#pragma unroll
    for (int i = 0; i < 4; ++i) {
        const int t = q0 + ty * 4 + i;
        const float inv = 1.0f / l_i[i];
#pragma unroll
        for (int j = 0; j < 4; ++j)
            g_O[((size_t)(b * SEQ + t)) * EMBED + h * HDIM + tx * 4 + j] =
                o_[i][j] * inv;
    }
}

// ---------------------------------------------------------------------------
extern "C" void kernel_launch(void* const* d_in, const int* in_sizes, int n_in,
                              void* d_out, int out_size)
{
    const float* x      = (const float*)d_in[0];
    const float* w_qkv  = (const float*)d_in[1];
    const float* b_qkv  = (const float*)d_in[2];
    const float* w_proj = (const float*)d_in[3];
    const float* b_proj = (const float*)d_in[4];
    float* out = (float*)d_out;

    float* gO = nullptr;
    cudaGetSymbolAddress((void**)&gO, g_O);

    // 1) QKV projection (tf32 mma, scatter into g_Q/g_K/g_V)
    {
        dim3 grid(QKVN / 128, MTOK / 128);
        gemm_mma<0><<<grid, 256>>>(x, w_qkv, b_qkv, nullptr, MTOK, QKVN, EMBED);
    }
    // 2) Flash attention -> g_O
    {
        dim3 grid(SEQ / 64, BATCH * HEADS);
        flash_attn<<<grid, 256>>>();
    }
    // 3) Output projection (tf32 mma)
    {
        dim3 grid(EMBED / 128, MTOK / 128);
        gemm_mma<1><<<grid, 256>>>(gO, w_proj, b_proj, out, MTOK, EMBED, EMBED);
    }
}

// round 3
// speedup vs baseline: 2.6900x; 1.8264x over previous
#include <cuda_runtime.h>

// ---------------------------------------------------------------------------
// Fused MHA block, all matmuls on tf32 tensor cores (legacy mma.sync path):
//   QKV GEMM (tf32) -> flash attention (tf32 mma, K-split compensated) -> proj.
// Shapes: B=2, N=2048, EMBED=1024, HEADS=16, HDIM=64.
// ---------------------------------------------------------------------------

#define BATCH  2
#define SEQ    2048
#define EMBED  1024
#define HEADS  16
#define HDIM   64
#define MTOK   (BATCH * SEQ)      // 4096
#define QKVN   (3 * EMBED)        // 3072
#define SCALE  0.125f             // HDIM^-0.5

__device__ float g_Q[BATCH * HEADS * SEQ * HDIM];   // [B,H,N,Dh]
__device__ float g_K[BATCH * HEADS * SEQ * HDIM];
__device__ float g_V[BATCH * HEADS * SEQ * HDIM];
__device__ float g_O[BATCH * SEQ * EMBED];          // attention output [B,N,EMBED]

// ---------------------------------------------------------------------------
__device__ __forceinline__ unsigned f2tf(float f) {
    unsigned r;
    asm("cvt.rna.tf32.f32 %0, %1;" : "=r"(r) : "f"(f));
    return r;
}

__device__ __forceinline__ void mma_tf32(float* c, const unsigned* a, const unsigned* b) {
    asm volatile(
        "mma.sync.aligned.m16n8k8.row.col.f32.tf32.tf32.f32 "
        "{%0,%1,%2,%3}, {%4,%5,%6,%7}, {%8,%9}, {%0,%1,%2,%3};\n"
        : "+f"(c[0]), "+f"(c[1]), "+f"(c[2]), "+f"(c[3])
        : "r"(a[0]), "r"(a[1]), "r"(a[2]), "r"(a[3]),
          "r"(b[0]), "r"(b[1]));
}

// ---------------------------------------------------------------------------
// GEMM: C[M,N] = A[M,K] @ W[N,K]^T + bias[N]   (tf32 tensor cores)
// Unchanged from round 2.
// ---------------------------------------------------------------------------
template <int MODE>
__global__ __launch_bounds__(256)
void gemm_mma(const float* __restrict__ A, const float* __restrict__ W,
              const float* __restrict__ bias, float* __restrict__ out,
              int M, int N, int K)
{
    constexpr int BM = 128, BN = 128, BK = 32;
    constexpr int LDT = BK + 4;
    __shared__ unsigned As[BM * LDT];
    __shared__ unsigned Bs[BN * LDT];

    const int tid  = threadIdx.x;
    const int wid  = tid >> 5;
    const int lane = tid & 31;
    const int g    = lane >> 2;
    const int t    = lane & 3;

    const int wm0 = (wid & 3) * 32;
    const int wn0 = (wid >> 2) * 64;

    const int m0 = blockIdx.y * BM;
    const int n0 = blockIdx.x * BN;

    float acc[2][8][4];
#pragma unroll
    for (int mi = 0; mi < 2; ++mi)
#pragma unroll
        for (int nj = 0; nj < 8; ++nj)
#pragma unroll
            for (int r = 0; r < 4; ++r) acc[mi][nj][r] = 0.f;

    const int srow = tid >> 3;
    const int scol = (tid & 7) * 4;

    for (int k0 = 0; k0 < K; k0 += BK) {
#pragma unroll
        for (int r = 0; r < 4; ++r) {
            const int row = srow + 32 * r;
            float4 a = *(const float4*)&A[(size_t)(m0 + row) * K + k0 + scol];
            uint4 at = make_uint4(f2tf(a.x), f2tf(a.y), f2tf(a.z), f2tf(a.w));
            *(uint4*)&As[row * LDT + scol] = at;
            float4 b = *(const float4*)&W[(size_t)(n0 + row) * K + k0 + scol];
            uint4 bt = make_uint4(f2tf(b.x), f2tf(b.y), f2tf(b.z), f2tf(b.w));
            *(uint4*)&Bs[row * LDT + scol] = bt;
        }
        __syncthreads();

#pragma unroll
        for (int ks = 0; ks < BK / 8; ++ks) {
            const int kk = ks * 8;
            unsigned a[2][4], b[8][2];
#pragma unroll
            for (int mi = 0; mi < 2; ++mi) {
                const int mb = wm0 + mi * 16;
                a[mi][0] = As[(mb + g)     * LDT + kk + t];
                a[mi][1] = As[(mb + g + 8) * LDT + kk + t];
                a[mi][2] = As[(mb + g)     * LDT + kk + t + 4];
                a[mi][3] = As[(mb + g + 8) * LDT + kk + t + 4];
            }
#pragma unroll
            for (int nj = 0; nj < 8; ++nj) {
                const int nb = wn0 + nj * 8 + g;
                b[nj][0] = Bs[nb * LDT + kk + t];
                b[nj][1] = Bs[nb * LDT + kk + t + 4];
            }
#pragma unroll
            for (int mi = 0; mi < 2; ++mi)
#pragma unroll
                for (int nj = 0; nj < 8; ++nj)
                    mma_tf32(acc[mi][nj], a[mi], b[nj]);
        }
        __syncthreads();
    }

#pragma unroll
    for (int mi = 0; mi < 2; ++mi) {
#pragma unroll
        for (int nj = 0; nj < 8; ++nj) {
#pragma unroll
            for (int r = 0; r < 4; ++r) {
                const int m = m0 + wm0 + mi * 16 + g + (r >= 2 ? 8 : 0);
                const int n = n0 + wn0 + nj * 8 + 2 * t + (r & 1);
                float v = acc[mi][nj][r] + bias[n];
                if (MODE == 0) {
                    const int which = n >> 10;
                    const int rem   = n & 1023;
                    const int h     = rem >> 6;
                    const int dh    = rem & 63;
                    const int b_    = m >> 11;
                    const int tkn   = m & 2047;
                    float* dst = (which == 0) ? g_Q : (which == 1) ? g_K : g_V;
                    dst[(((size_t)(b_ * HEADS + h) * SEQ) + tkn) * HDIM + dh] = v;
                } else {
                    out[(size_t)m * N + n] = v;
                }
            }
        }
    }
}

// ---------------------------------------------------------------------------
// Flash attention on tf32 mma. One CTA per (bh, 128 q-rows); 8 warps each own
// 16 q-rows x 64 kv-cols. KV tile 64. S = Qb*Kb + Qb*Ks (K-split compensated).
// P staged through smem (tf32), overlaying the K tiles. LD=68 words keeps all
// fragment LDS accesses bank-conflict-free ((4g+t) mod 32 is a permutation).
// ---------------------------------------------------------------------------
#define ALD 68                      // padded row stride (words)
#define SM_Q 0                      // Qb  [128][ALD]
#define SM_K (128 * ALD)            // Kb [64][ALD], Ks [64][ALD]; P overlays [128][ALD]
#define SM_V (2 * 128 * ALD)        // Vs [64][ALD] (tf32)
#define SM_WORDS (SM_V + 64 * ALD)  // 21760 words = 87040 bytes

__global__ __launch_bounds__(256, 2)
void flash_attn_mma()
{
    extern __shared__ unsigned sm[];
    unsigned* Qb = sm + SM_Q;
    unsigned* KP = sm + SM_K;   // K tiles / P staging (aliased, fenced by syncs)
    unsigned* Vs = sm + SM_V;

    const int bh = blockIdx.y;
    const int q0 = blockIdx.x * 128;
    const float* Qp = g_Q + (size_t)bh * SEQ * HDIM;
    const float* Kp = g_K + (size_t)bh * SEQ * HDIM;
    const float* Vp = g_V + (size_t)bh * SEQ * HDIM;

    const int tid  = threadIdx.x;
    const int wid  = tid >> 5;
    const int lane = tid & 31;
    const int g    = lane >> 2;
    const int t    = lane & 3;
    const int arow = wid * 16;          // warp's first q-row in tile

    // Prologue: load Q tile (scaled) -> tf32 smem.
#pragma unroll
    for (int it = 0; it < 8; ++it) {
        const int idx = tid + 256 * it;      // over 128 rows x 16 float4
        const int r = idx >> 4;
        const int c = (idx & 15) * 4;
        float4 q = *(const float4*)&Qp[(size_t)(q0 + r) * HDIM + c];
        Qb[r * ALD + c + 0] = f2tf(q.x * SCALE);
        Qb[r * ALD + c + 1] = f2tf(q.y * SCALE);
        Qb[r * ALD + c + 2] = f2tf(q.z * SCALE);
        Qb[r * ALD + c + 3] = f2tf(q.w * SCALE);
    }

    float o[8][4];
    float mrow[2] = {-1e30f, -1e30f};
    float lrow[2] = {0.f, 0.f};
#pragma unroll
    for (int nj = 0; nj < 8; ++nj)
#pragma unroll
        for (int r = 0; r < 4; ++r) o[nj][r] = 0.f;

    const unsigned FULL = 0xffffffffu;

    for (int kt = 0; kt < SEQ / 64; ++kt) {
        __syncthreads();   // prior PV reads of KP/Vs complete
        // Load K (split into Kb + Ks) and V (tf32) tiles.
#pragma unroll
        for (int it = 0; it < 4; ++it) {
            const int idx = tid + 256 * it;   // over 64 rows x 16 float4
            const int r = idx >> 4;
            const int c = (idx & 15) * 4;
            float4 kk = *(const float4*)&Kp[(size_t)(kt * 64 + r) * HDIM + c];
            float kf[4] = {kk.x, kk.y, kk.z, kk.w};
#pragma unroll
            for (int e = 0; e < 4; ++e) {
                unsigned kb = f2tf(kf[e]);
                KP[r * ALD + c + e] = kb;
                KP[(64 + r) * ALD + c + e] = f2tf(kf[e] - __uint_as_float(kb));
            }
            float4 vv = *(const float4*)&Vp[(size_t)(kt * 64 + r) * HDIM + c];
            Vs[r * ALD + c + 0] = f2tf(vv.x);
            Vs[r * ALD + c + 1] = f2tf(vv.y);
            Vs[r * ALD + c + 2] = f2tf(vv.z);
            Vs[r * ALD + c + 3] = f2tf(vv.w);
        }
        __syncthreads();

        // S = Qb @ (Kb + Ks)^T    (M16 x N64 per warp, K=64)
        float s[8][4];
#pragma unroll
        for (int nj = 0; nj < 8; ++nj)
#pragma unroll
            for (int r = 0; r < 4; ++r) s[nj][r] = 0.f;

#pragma unroll
        for (int ks8 = 0; ks8 < 8; ++ks8) {
            const int kk = ks8 * 8;
            unsigned a[4];
            a[0] = Qb[(arow + g)     * ALD + kk + t];
            a[1] = Qb[(arow + g + 8) * ALD + kk + t];
            a[2] = Qb[(arow + g)     * ALD + kk + t + 4];
            a[3] = Qb[(arow + g + 8) * ALD + kk + t + 4];
#pragma unroll
            for (int nj = 0; nj < 8; ++nj) {
                const int nb = nj * 8 + g;
                unsigned bb[2], bs[2];
                bb[0] = KP[nb * ALD + kk + t];
                bb[1] = KP[nb * ALD + kk + t + 4];
                bs[0] = KP[(64 + nb) * ALD + kk + t];
                bs[1] = KP[(64 + nb) * ALD + kk + t + 4];
                mma_tf32(s[nj], a, bb);
                mma_tf32(s[nj], a, bs);
            }
        }

        // Online softmax: two rows per thread-quad (g and g+8).
#pragma unroll
        for (int h = 0; h < 2; ++h) {
            const int r0 = 2 * h;                // regs {0,1} or {2,3}
            float mx = -1e30f;
#pragma unroll
            for (int nj = 0; nj < 8; ++nj)
                mx = fmaxf(mx, fmaxf(s[nj][r0], s[nj][r0 + 1]));
            mx = fmaxf(mx, __shfl_xor_sync(FULL, mx, 1));
            mx = fmaxf(mx, __shfl_xor_sync(FULL, mx, 2));
            const float mnew = fmaxf(mrow[h], mx);
            const float alpha = __expf(mrow[h] - mnew);
            float rs = 0.f;
#pragma unroll
            for (int nj = 0; nj < 8; ++nj) {
                s[nj][r0]     = __expf(s[nj][r0]     - mnew);
                s[nj][r0 + 1] = __expf(s[nj][r0 + 1] - mnew);
                rs += s[nj][r0] + s[nj][r0 + 1];
            }
            rs += __shfl_xor_sync(FULL, rs, 1);
            rs += __shfl_xor_sync(FULL, rs, 2);
            lrow[h] = alpha * lrow[h] + rs;
            mrow[h] = mnew;
#pragma unroll
            for (int nj = 0; nj < 8; ++nj) {
                o[nj][r0]     *= alpha;
                o[nj][r0 + 1] *= alpha;
            }
        }

        __syncthreads();   // all warps done reading K tiles; KP becomes P

        // Stage P (tf32) as [128][ALD].
#pragma unroll
        for (int nj = 0; nj < 8; ++nj) {
            uint2 p0 = make_uint2(f2tf(s[nj][0]), f2tf(s[nj][1]));
            *(uint2*)&KP[(arow + g) * ALD + nj * 8 + 2 * t] = p0;
            uint2 p1 = make_uint2(f2tf(s[nj][2]), f2tf(s[nj][3]));
            *(uint2*)&KP[(arow + g + 8) * ALD + nj * 8 + 2 * t] = p1;
        }
        __syncthreads();

        // O += P @ V   (K = 64 kv)
#pragma unroll
        for (int ks8 = 0; ks8 < 8; ++ks8) {
            const int kk = ks8 * 8;
            unsigned a[4];
            a[0] = KP[(arow + g)     * ALD + kk + t];
            a[1] = KP[(arow + g + 8) * ALD + kk + t];
            a[2] = KP[(arow + g)     * ALD + kk + t + 4];
            a[3] = KP[(arow + g + 8) * ALD + kk + t + 4];
#pragma unroll
            for (int nj = 0; nj < 8; ++nj) {
                unsigned b[2];
                b[0] = Vs[(kk + t)     * ALD + nj * 8 + g];
                b[1] = Vs[(kk + t + 4) * ALD + nj * 8 + g];
                mma_tf32(o[nj], a, b);
            }
        }
    }

    // Epilogue: normalize, write to g_O [B,N,EMBED].
    const int h  = bh & (HEADS - 1);
    const int b  = bh >> 4;
    const float inv0 = 1.0f / lrow[0];
    const float inv1 = 1.0f / lrow[1];
    const int r0 = q0 + arow + g;
#pragma unroll
    for (int nj = 0; nj < 8; ++nj) {
        const int col = h * HDIM + nj * 8 + 2 * t;
        float2 v0 = make_float2(o[nj][0] * inv0, o[nj][1] * inv0);
        *(float2*)&g_O[(size_t)(b * SEQ + r0) * EMBED + col] = v0;
        float2 v1 = make_float2(o[nj][2] * inv1, o[nj][3] * inv1);
        *(float2*)&g_O[(size_t)(b * SEQ + r0 + 8) * EMBED + col] = v1;
    }
}

// ---------------------------------------------------------------------------
extern "C" void kernel_launch(void* const* d_in, const int* in_sizes, int n_in,
                              void* d_out, int out_size)
{
    const float* x      = (const float*)d_in[0];
    const float* w_qkv  = (const float*)d_in[1];
    const float* b_qkv  = (const float*)d_in[2];
    const float* w_proj = (const float*)d_in[3];
    const float* b_proj = (const float*)d_in[4];
    float* out = (float*)d_out;

    float* gO = nullptr;
    cudaGetSymbolAddress((void**)&gO, g_O);

    static bool attr_set = false;
    if (!attr_set) {
        cudaFuncSetAttribute(flash_attn_mma,
                             cudaFuncAttributeMaxDynamicSharedMemorySize,
                             SM_WORDS * 4);
        attr_set = true;
    }

    // 1) QKV projection (tf32 mma, scatter into g_Q/g_K/g_V)
    {
        dim3 grid(QKVN / 128, MTOK / 128);
        gemm_mma<0><<<grid, 256>>>(x, w_qkv, b_qkv, nullptr, MTOK, QKVN, EMBED);
    }
    // 2) Flash attention (tf32 mma) -> g_O
    {
        dim3 grid(SEQ / 128, BATCH * HEADS);
        flash_attn_mma<<<grid, 256, SM_WORDS * 4>>>();
    }
    // 3) Output projection (tf32 mma)
    {
        dim3 grid(EMBED / 128, MTOK / 128);
        gemm_mma<1><<<grid, 256>>>(gO, w_proj, b_proj, out, MTOK, EMBED, EMBED);
    }
}